// round 16
// baseline (speedup 1.0000x reference)
#include <cuda_runtime.h>

// DegreePrediction: y[u] = sum_{s,t,v} (x*W_t)[s,t] * (W_r*r_zeros + r_const)[s,t,u,v]
// N = 80. Three 80^4 fp32 tensors (491.5 MB) streamed once.
//
// R16: depth-3 prefetch pipeline at 3 blocks/SM. R15 (depth-2, 6.80 TB/s)
// confirmed the in-flight-depth model, and its demand (~720 sectors/SM)
// exactly matched delivery -> still supply-limited. Depth-3 raises demand to
// ~1080 sectors/SM. __launch_bounds__(320,3) caps regs at 68 to preserve
// 3 blocks/SM; a[] per-slice scalars computed inline (not hoisted) to help
// ptxas fit. Epilogue/finalize identical to R7/R15.
//
// Layout: slice = 1600 contiguous float4 = 5*320; iter it (k=it/5, j=it%5)
// reads float4 tid + 320*j + 1600*k -> u = tid/20 + 16*j.

#define NN 80
#define SLICE_F4 1600
#define SLICE_FLOATS (NN * NN)      // 6400
#define THREADS 320
#define J_ITERS 5
#define K_SLICES 4
#define NITER (K_SLICES * J_ITERS)  // 20
#define DEPTH 3
#define NUM_BLOCKS ((NN * NN) / K_SLICES)   // 1600

__device__ float    g_scratch[NN];   // zero at load; kernel restores to zero
__device__ unsigned g_count;         // ditto

__device__ __forceinline__ unsigned atom_inc_acq_rel(unsigned* p) {
    unsigned old;
    asm volatile("atom.add.acq_rel.gpu.global.u32 %0, [%1], 1;"
                 : "=r"(old) : "l"(p) : "memory");
    return old;
}

__global__ __launch_bounds__(THREADS, 3)
void degree_pred_kernel(const float* __restrict__ x,
                        const float* __restrict__ r_zeros,
                        const float* __restrict__ r_const,
                        const float* __restrict__ weights_t,
                        const float* __restrict__ weights_r,
                        float* __restrict__ out)
{
    __shared__ float y_part[J_ITERS][THREADS];
    __shared__ bool is_last;
    const int tid = threadIdx.x;

    const int st0 = blockIdx.x * K_SLICES;

    float acc[J_ITERS];
#pragma unroll
    for (int j = 0; j < J_ITERS; j++) acc[j] = 0.0f;

    const size_t base0 = (size_t)st0 * SLICE_FLOATS;
    const float4* __restrict__ rz = reinterpret_cast<const float4*>(r_zeros   + base0);
    const float4* __restrict__ rc = reinterpret_cast<const float4*>(r_const   + base0);
    const float4* __restrict__ wr = reinterpret_cast<const float4*>(weights_r + base0);

    // triple-buffered prefetch registers, depth 3
    float4 zb[DEPTH], cb[DEPTH], wb[DEPTH];
#pragma unroll
    for (int s = 0; s < DEPTH; s++) {
        const int p = tid + THREADS * s;      // it = s (all inside slice 0)
        zb[s] = __ldcs(&rz[p]);
        cb[s] = __ldcs(&rc[p]);
        wb[s] = __ldcs(&wr[p]);
    }

#pragma unroll
    for (int it = 0; it < NITER; it++) {
        const int cur = it % DEPTH;
        const int k = it / J_ITERS;
        const int j = it % J_ITERS;

        // per-slice scalar computed inline (k is compile-time per iteration;
        // __ldg is L1-hot after first use, and these sit behind the pipeline)
        const float a = __ldg(&x[st0 + k]) * __ldg(&weights_t[st0 + k]);

        const float4 z = zb[cur];
        const float4 c = cb[cur];
        const float4 w = wb[cur];

        // refill this slot with iteration it+DEPTH (compile-time offset)
        if (it + DEPTH < NITER) {
            const int itn = it + DEPTH;
            const int pn = tid + THREADS * (itn % J_ITERS) + SLICE_F4 * (itn / J_ITERS);
            zb[cur] = __ldcs(&rz[pn]);
            cb[cur] = __ldcs(&rc[pn]);
            wb[cur] = __ldcs(&wr[pn]);
        }

        float t = (c.x + c.y) + (c.z + c.w);
        t = fmaf(w.x, z.x, t);
        t = fmaf(w.y, z.y, t);
        t = fmaf(w.z, z.z, t);
        t = fmaf(w.w, z.w, t);
        acc[j] = fmaf(a, t, acc[j]);
    }

    // ---- epilogue (once per block): STS transpose + 80-thread gather ----
#pragma unroll
    for (int j = 0; j < J_ITERS; j++)
        y_part[j][tid] = acc[j];
    __syncthreads();

    if (tid < NN) {
        const int u = tid;
        const int j = u >> 4;            // u / 16
        const int b = (u & 15) * 20;     // first of 20 contributing threads
        float s = 0.0f;
#pragma unroll
        for (int d = 0; d < 20; d++)
            s += y_part[j][b + d];
        atomicAdd(&g_scratch[u], s);     // relaxed; published by acq_rel below
    }
    __syncthreads();

    // ---- last-block finalize ----
    if (tid == 0)
        is_last = (atom_inc_acq_rel(&g_count) == (unsigned)(NUM_BLOCKS - 1));
    __syncthreads();

    if (is_last) {
        if (tid < NN) {
            float v = __ldcg(&g_scratch[tid]);   // L2 read, coherent w/ atomics
            out[tid] = v;
            g_scratch[tid] = 0.0f;               // restore initial state
        }
        __syncthreads();
        if (tid == 0) g_count = 0u;              // restore initial state
    }
}

extern "C" void kernel_launch(void* const* d_in, const int* in_sizes, int n_in,
                              void* d_out, int out_size)
{
    const float* x         = (const float*)d_in[0];
    const float* r_zeros   = (const float*)d_in[1];
    const float* r_const   = (const float*)d_in[2];
    const float* weights_t = (const float*)d_in[3];
    const float* weights_r = (const float*)d_in[4];
    float* out = (float*)d_out;

    degree_pred_kernel<<<NUM_BLOCKS, THREADS>>>(x, r_zeros, r_const,
                                                weights_t, weights_r, out);
}